// round 4
// baseline (speedup 1.0000x reference)
#include <cuda_runtime.h>

#define H 128
#define HH (H * H)
#define TILE_N 64
#define NTG 128       // GEMM block threads
#define NT 256
#define MAXN 50176
#define MAXE 800000

typedef unsigned long long ull;

// Scratch (device globals — no allocation allowed)
__device__ float g_h0[(size_t)MAXN * H];
__device__ float g_agg[(size_t)MAXN * H];   // normalized neighbor mean
__device__ float g_x1[(size_t)MAXN * H];
__device__ float g_wt[5 * HH];              // transposed weights: [k][j]
__device__ int   g_cnt[MAXN];               // degree, then fill cursor
__device__ int   g_off[MAXN + 1];           // CSR offsets
__device__ int   g_csr[MAXE];               // CSR src lists (grouped by tgt)

// ---------------------------------------------------------------------------
// f32x2 helpers (FFMA2 — packed fp32 pairs, 2 MACs per fma-pipe slot)
// ---------------------------------------------------------------------------
__device__ __forceinline__ ull splat2(float x) {
    ull d;
    asm("mov.b64 %0, {%1, %1};" : "=l"(d) : "f"(x));
    return d;
}
__device__ __forceinline__ void fma2(ull& acc, ull a, ull b) {
    asm("fma.rn.f32x2 %0, %1, %2, %0;" : "+l"(acc) : "l"(a), "l"(b));
}
__device__ __forceinline__ void unpack2(ull v, float& lo, float& hi) {
    asm("mov.b64 {%0, %1}, %2;" : "=f"(lo), "=f"(hi) : "l"(v));
}

// ---------------------------------------------------------------------------
// Transpose all five W[j][k] ([H,H] row-major) into g_wt slots as Wt[k][j].
// ---------------------------------------------------------------------------
__global__ void transpose_w_all(const float* __restrict__ W0,
                                const float* __restrict__ W1,
                                const float* __restrict__ W2,
                                const float* __restrict__ W3,
                                const float* __restrict__ W4) {
    int slot = blockIdx.y;
    const float* W = (slot == 0) ? W0 : (slot == 1) ? W1 : (slot == 2) ? W2
                   : (slot == 3) ? W3 : W4;
    int idx = blockIdx.x * blockDim.x + threadIdx.x;
    if (idx < HH) {
        int j = idx >> 7;
        int k = idx & 127;
        g_wt[slot * HH + k * H + j] = W[idx];
    }
}

// ---------------------------------------------------------------------------
// CSR build: zero counters, histogram, scan, fill
// ---------------------------------------------------------------------------
__global__ void zero_cnt(int N) {
    int i = blockIdx.x * blockDim.x + threadIdx.x;
    if (i < N) g_cnt[i] = 0;
}

__global__ void deg_hist(const int* __restrict__ ei, int E) {
    int e = blockIdx.x * blockDim.x + threadIdx.x;
    if (e < E) atomicAdd(&g_cnt[ei[E + e]], 1);
}

// Single-block exclusive scan of g_cnt[0..N) -> g_off; g_off[N] = E.
__global__ void scan_kernel(int N, int E) {
    __shared__ int ps[1024];
    const int tid = threadIdx.x;
    const int chunk = (N + 1023) >> 10;
    const int lo = tid * chunk;
    const int hi = min(lo + chunk, N);
    int sum = 0;
    for (int i = lo; i < hi; i++) sum += g_cnt[i];
    ps[tid] = sum;
    __syncthreads();
    for (int off = 1; off < 1024; off <<= 1) {
        int v = (tid >= off) ? ps[tid - off] : 0;
        __syncthreads();
        ps[tid] += v;
        __syncthreads();
    }
    int base = ps[tid] - sum;  // exclusive
    for (int i = lo; i < hi; i++) {
        g_off[i] = base;
        base += g_cnt[i];
    }
    if (tid == 0) g_off[N] = E;
}

__global__ void csr_fill(const int* __restrict__ ei, int E) {
    int e = blockIdx.x * blockDim.x + threadIdx.x;
    if (e >= E) return;
    int s = ei[e];
    int t = ei[E + e];
    int pos = atomicAdd(&g_cnt[t], -1) - 1;   // unique slot in [0, deg)
    g_csr[g_off[t] + pos] = s;
}

// ---------------------------------------------------------------------------
// Aggregation: one warp per node; gather h[src] rows via CSR, write mean.
// ---------------------------------------------------------------------------
__global__ void gather_agg(int xsel, int N) {
    int gt = blockIdx.x * blockDim.x + threadIdx.x;
    int node = gt >> 5;
    if (node >= N) return;
    int lane = gt & 31;
    const float* h = xsel ? g_x1 : g_h0;

    int beg = g_off[node];
    int end = g_off[node + 1];
    float4 a0 = make_float4(0.f, 0.f, 0.f, 0.f);
    float4 a1 = make_float4(0.f, 0.f, 0.f, 0.f);

    for (int base = beg; base < end; base += 32) {
        int nchunk = min(32, end - base);
        int s_l = (base + lane < end) ? g_csr[base + lane] : 0;
        int j = 0;
        for (; j + 1 < nchunk; j += 2) {
            int s0 = __shfl_sync(0xffffffffu, s_l, j);
            int s1 = __shfl_sync(0xffffffffu, s_l, j + 1);
            float4 v0 = *(const float4*)(h + (size_t)s0 * H + (lane << 2));
            float4 v1 = *(const float4*)(h + (size_t)s1 * H + (lane << 2));
            a0.x += v0.x; a0.y += v0.y; a0.z += v0.z; a0.w += v0.w;
            a1.x += v1.x; a1.y += v1.y; a1.z += v1.z; a1.w += v1.w;
        }
        if (j < nchunk) {
            int s0 = __shfl_sync(0xffffffffu, s_l, j);
            float4 v0 = *(const float4*)(h + (size_t)s0 * H + (lane << 2));
            a0.x += v0.x; a0.y += v0.y; a0.z += v0.z; a0.w += v0.w;
        }
    }
    float inv = 1.0f / (float)max(end - beg, 1);
    float4 r = make_float4((a0.x + a1.x) * inv, (a0.y + a1.y) * inv,
                           (a0.z + a1.z) * inv, (a0.w + a1.w) * inv);
    *(float4*)(g_agg + (size_t)node * H + (lane << 2)) = r;
}

// ---------------------------------------------------------------------------
// Register-tiled accumulate with FFMA2: 8 nodes x 8 outputs per thread.
// NTG=128 threads: jt = tid&15 (j groups), nt = tid>>4 (8 n-groups of 8).
// ---------------------------------------------------------------------------
__device__ __forceinline__ void mm_accum8(const float* __restrict__ Xs,
                                          const float* __restrict__ Ws,
                                          int n0, int jlo, ull acc[8][4]) {
#pragma unroll
    for (int k4 = 0; k4 < H; k4 += 4) {
        float4 xv[8];
#pragma unroll
        for (int i = 0; i < 8; i++)
            xv[i] = *(const float4*)(Xs + (n0 + i) * H + k4);
#pragma unroll
        for (int kk = 0; kk < 4; kk++) {
            const int k = k4 + kk;
            ulonglong2 wa = *(const ulonglong2*)(Ws + k * H + jlo);
            ulonglong2 wb = *(const ulonglong2*)(Ws + k * H + jlo + 64);
#pragma unroll
            for (int i = 0; i < 8; i++) {
                float xs = (kk == 0) ? xv[i].x : (kk == 1) ? xv[i].y
                         : (kk == 2) ? xv[i].z : xv[i].w;
                ull x2 = splat2(xs);
                fma2(acc[i][0], x2, wa.x);
                fma2(acc[i][1], x2, wa.y);
                fma2(acc[i][2], x2, wb.x);
                fma2(acc[i][3], x2, wb.y);
            }
        }
    }
}

// ---------------------------------------------------------------------------
// Input layer: h0 = relu( concat(attr,cc,bl,exist) @ W_in^T + b_in )
// ---------------------------------------------------------------------------
__global__ void __launch_bounds__(NTG, 2)
input_gemm(const float* __restrict__ attr, int ATTR,
           const float* __restrict__ cc,
           const float* __restrict__ bl,
           const float* __restrict__ exist,
           const float* __restrict__ b, int N) {
    extern __shared__ float sm[];
    float* Xs = sm;              // TILE_N * H
    float* Ws = sm + TILE_N * H; // HH
    const int tid = threadIdx.x;
    const int nb = blockIdx.x * TILE_N;

    for (int idx = tid; idx < HH / 4; idx += NTG)
        ((float4*)Ws)[idx] = ((const float4*)g_wt)[idx];  // slot 0

    for (int idx = tid; idx < TILE_N * H; idx += NTG) {
        int n = idx >> 7, k = idx & 127;
        int gn = nb + n;
        float v = 0.f;
        if (gn < N) {
            if (k < ATTR)            v = attr[(size_t)gn * ATTR + k];
            else if (k == ATTR)      v = cc[gn];
            else if (k == ATTR + 1)  v = bl[gn];
            else if (k == ATTR + 2)  v = exist[gn];
        }
        Xs[idx] = v;
    }
    __syncthreads();

    const int jt = tid & 15, nt = tid >> 4;
    const int jlo = jt * 4, n0 = nt * 8;
    ull acc[8][4] = {};
    mm_accum8(Xs, Ws, n0, jlo, acc);

#pragma unroll
    for (int i = 0; i < 8; i++) {
        int gn = nb + n0 + i;
        if (gn >= N) continue;
        float o[8];
        unpack2(acc[i][0], o[0], o[1]);
        unpack2(acc[i][1], o[2], o[3]);
        unpack2(acc[i][2], o[4], o[5]);
        unpack2(acc[i][3], o[6], o[7]);
        float4 o1, o2;
        o1.x = fmaxf(o[0] + b[jlo + 0], 0.f);
        o1.y = fmaxf(o[1] + b[jlo + 1], 0.f);
        o1.z = fmaxf(o[2] + b[jlo + 2], 0.f);
        o1.w = fmaxf(o[3] + b[jlo + 3], 0.f);
        o2.x = fmaxf(o[4] + b[jlo + 64], 0.f);
        o2.y = fmaxf(o[5] + b[jlo + 65], 0.f);
        o2.z = fmaxf(o[6] + b[jlo + 66], 0.f);
        o2.w = fmaxf(o[7] + b[jlo + 67], 0.f);
        *(float4*)(g_h0 + (size_t)gn * H + jlo) = o1;
        *(float4*)(g_h0 + (size_t)gn * H + jlo + 64) = o2;
    }
}

// ---------------------------------------------------------------------------
// SAGE layer: out = post( X@Ws^T + bs + mean@Wn^T + bn ); g_agg holds mean.
// ---------------------------------------------------------------------------
__global__ void __launch_bounds__(NTG, 2)
sage_gemm(int xsel, int wslot_self, int wslot_neigh,
          const float* __restrict__ bs,
          const float* __restrict__ bn,
          const float* __restrict__ exist,
          float* out, int N, int do_relu) {
    extern __shared__ float sm[];
    float* Xs = sm;
    float* Ws = sm + TILE_N * H;
    const int tid = threadIdx.x;
    const int nb = blockIdx.x * TILE_N;
    const int jt = tid & 15, nt = tid >> 4;
    const int jlo = jt * 4, n0 = nt * 8;
    const float* Xself = xsel ? g_x1 : g_h0;
    float* dst = out ? out : g_x1;

    ull acc[8][4] = {};

    // phase 1: self term
    for (int idx = tid; idx < HH / 4; idx += NTG)
        ((float4*)Ws)[idx] = ((const float4*)(g_wt + wslot_self * HH))[idx];
    for (int idx = tid; idx < TILE_N * (H / 4); idx += NTG) {
        int n = idx >> 5, kq = idx & 31;
        int gn = nb + n;
        float4 v = make_float4(0.f, 0.f, 0.f, 0.f);
        if (gn < N) v = *(const float4*)(Xself + (size_t)gn * H + kq * 4);
        *(float4*)(Xs + n * H + kq * 4) = v;
    }
    __syncthreads();
    mm_accum8(Xs, Ws, n0, jlo, acc);
    __syncthreads();

    // phase 2: neighbor-mean term (g_agg already normalized)
    for (int idx = tid; idx < HH / 4; idx += NTG)
        ((float4*)Ws)[idx] = ((const float4*)(g_wt + wslot_neigh * HH))[idx];
    for (int idx = tid; idx < TILE_N * (H / 4); idx += NTG) {
        int n = idx >> 5, kq = idx & 31;
        int gn = nb + n;
        float4 v = make_float4(0.f, 0.f, 0.f, 0.f);
        if (gn < N) v = *(const float4*)(g_agg + (size_t)gn * H + kq * 4);
        *(float4*)(Xs + n * H + kq * 4) = v;
    }
    __syncthreads();
    mm_accum8(Xs, Ws, n0, jlo, acc);

#pragma unroll
    for (int i = 0; i < 8; i++) {
        int gn = nb + n0 + i;
        if (gn >= N) continue;
        float ex = exist[gn];
        float o[8];
        unpack2(acc[i][0], o[0], o[1]);
        unpack2(acc[i][1], o[2], o[3]);
        unpack2(acc[i][2], o[4], o[5]);
        unpack2(acc[i][3], o[6], o[7]);
        float r[8];
#pragma unroll
        for (int q = 0; q < 4; q++) {
            float v1 = o[q] + bs[jlo + q] + bn[jlo + q];
            float v2 = o[q + 4] + bs[jlo + 64 + q] + bn[jlo + 64 + q];
            if (do_relu) { v1 = fmaxf(v1, 0.f); v2 = fmaxf(v2, 0.f); }
            r[q] = v1 * ex;
            r[q + 4] = v2 * ex;
        }
        *(float4*)(dst + (size_t)gn * H + jlo) = make_float4(r[0], r[1], r[2], r[3]);
        *(float4*)(dst + (size_t)gn * H + jlo + 64) = make_float4(r[4], r[5], r[6], r[7]);
    }
}

// ---------------------------------------------------------------------------
extern "C" void kernel_launch(void* const* d_in, const int* in_sizes, int n_in,
                              void* d_out, int out_size) {
    const float* attr  = (const float*)d_in[0];
    const float* cc    = (const float*)d_in[1];
    const float* bl    = (const float*)d_in[2];
    const float* exist = (const float*)d_in[3];
    const float* W_in  = (const float*)d_in[4];
    const float* b_in  = (const float*)d_in[5];
    const float* W1s   = (const float*)d_in[6];
    const float* b1s   = (const float*)d_in[7];
    const float* W1n   = (const float*)d_in[8];
    const float* b1n   = (const float*)d_in[9];
    const float* W2s   = (const float*)d_in[10];
    const float* b2s   = (const float*)d_in[11];
    const float* W2n   = (const float*)d_in[12];
    const float* b2n   = (const float*)d_in[13];
    const int*   ei    = (const int*)d_in[14];   // int32 (JAX x64 disabled)

    const int N    = in_sizes[3];
    const int ATTR = in_sizes[0] / N;
    const int E    = in_sizes[14] / 2;
    float* out = (float*)d_out;

    const int SMEM = (TILE_N * H + HH) * (int)sizeof(float);
    cudaFuncSetAttribute(input_gemm, cudaFuncAttributeMaxDynamicSharedMemorySize, SMEM);
    cudaFuncSetAttribute(sage_gemm,  cudaFuncAttributeMaxDynamicSharedMemorySize, SMEM);

    const int gemm_grid = (N + TILE_N - 1) / TILE_N;
    const int edge_grid = (E + NT - 1) / NT;
    const int node_grid = (N + NT - 1) / NT;
    const long long ga_threads = (long long)N * 32;
    const int ga_grid = (int)((ga_threads + NT - 1) / NT);

    // weight transposes (slots: 0=W_in, 1=W1s, 2=W1n, 3=W2s, 4=W2n)
    dim3 tr_grid((HH + NT - 1) / NT, 5);
    transpose_w_all<<<tr_grid, NT>>>(W_in, W1s, W1n, W2s, W2n);

    // CSR build (shared by both layers)
    zero_cnt<<<node_grid, NT>>>(N);
    deg_hist<<<edge_grid, NT>>>(ei, E);
    scan_kernel<<<1, 1024>>>(N, E);
    csr_fill<<<edge_grid, NT>>>(ei, E);

    // input layer
    input_gemm<<<gemm_grid, NTG, SMEM>>>(attr, ATTR, cc, bl, exist, b_in, N);

    // layer 1
    gather_agg<<<ga_grid, NT>>>(0, N);
    sage_gemm<<<gemm_grid, NTG, SMEM>>>(0, 1, 2, b1s, b1n, exist, nullptr, N, 1);

    // layer 2
    gather_agg<<<ga_grid, NT>>>(1, N);
    sage_gemm<<<gemm_grid, NTG, SMEM>>>(1, 3, 4, b2s, b2n, exist, out, N, 0);
}

// round 5
// speedup vs baseline: 1.0783x; 1.0783x over previous
#include <cuda_runtime.h>

#define H 128
#define HH (H * H)
#define TILE_N 64
#define NTG 128       // GEMM block threads
#define NT 256
#define MAXN 50176
#define MAXE 800000
#define SCAN_BLK 256

typedef unsigned long long ull;

// Scratch (device globals — no allocation allowed)
__device__ float g_h0[(size_t)MAXN * H];
__device__ float g_agg[(size_t)MAXN * H];   // normalized neighbor mean
__device__ float g_x1[(size_t)MAXN * H];
__device__ float g_wt[5 * HH];              // transposed weights: [k][j]
__device__ int   g_cnt[MAXN];               // degree, then fill cursor
__device__ int   g_off[MAXN + 1];           // CSR offsets
__device__ int   g_csr[MAXE];               // CSR src lists (grouped by tgt)
__device__ int   g_bsum[(MAXN + SCAN_BLK - 1) / SCAN_BLK];

// ---------------------------------------------------------------------------
// f32x2 helpers (FFMA2 — packed fp32 pairs, 2 MACs per fma-pipe slot)
// ---------------------------------------------------------------------------
__device__ __forceinline__ ull splat2(float x) {
    ull d;
    asm("mov.b64 %0, {%1, %1};" : "=l"(d) : "f"(x));
    return d;
}
__device__ __forceinline__ void fma2(ull& acc, ull a, ull b) {
    asm("fma.rn.f32x2 %0, %1, %2, %0;" : "+l"(acc) : "l"(a), "l"(b));
}
__device__ __forceinline__ void unpack2(ull v, float& lo, float& hi) {
    asm("mov.b64 {%0, %1}, %2;" : "=f"(lo), "=f"(hi) : "l"(v));
}

// ---------------------------------------------------------------------------
// Transpose all five W[j][k] ([H,H] row-major) into g_wt slots as Wt[k][j].
// Also zeroes g_cnt (gridDim.y slot 0 handles it).
// ---------------------------------------------------------------------------
__global__ void transpose_w_all(const float* __restrict__ W0,
                                const float* __restrict__ W1,
                                const float* __restrict__ W2,
                                const float* __restrict__ W3,
                                const float* __restrict__ W4, int N) {
    int slot = blockIdx.y;
    const float* W = (slot == 0) ? W0 : (slot == 1) ? W1 : (slot == 2) ? W2
                   : (slot == 3) ? W3 : W4;
    int idx = blockIdx.x * blockDim.x + threadIdx.x;
    if (idx < HH) {
        int j = idx >> 7;
        int k = idx & 127;
        g_wt[slot * HH + k * H + j] = W[idx];
    }
    if (slot == 0) {
        // zero degree counters (HH = 16384 threads in y-slice 0; N <= 50176 needs loop)
        for (int i = idx; i < N; i += gridDim.x * blockDim.x) g_cnt[i] = 0;
    }
}

// ---------------------------------------------------------------------------
// CSR build: histogram, 3-phase parallel scan, fill
// ---------------------------------------------------------------------------
__global__ void deg_hist(const int* __restrict__ ei, int E) {
    int e = blockIdx.x * blockDim.x + threadIdx.x;
    if (e < E) atomicAdd(&g_cnt[ei[E + e]], 1);
}

// Phase A: per-block exclusive scan of 256 counts; block sum -> g_bsum
__global__ void scanA(int N) {
    __shared__ int sh[SCAN_BLK];
    int tid = threadIdx.x;
    int gi = blockIdx.x * SCAN_BLK + tid;
    int v = (gi < N) ? g_cnt[gi] : 0;
    sh[tid] = v;
    __syncthreads();
#pragma unroll
    for (int off = 1; off < SCAN_BLK; off <<= 1) {
        int t = (tid >= off) ? sh[tid - off] : 0;
        __syncthreads();
        sh[tid] += t;
        __syncthreads();
    }
    if (gi < N) g_off[gi] = sh[tid] - v;          // exclusive within block
    if (tid == SCAN_BLK - 1) g_bsum[blockIdx.x] = sh[tid];
}

// Phase B: single block exclusive scan of block sums (nblk <= 256)
__global__ void scanB(int nblk) {
    __shared__ int sh[SCAN_BLK];
    int tid = threadIdx.x;
    int v = (tid < nblk) ? g_bsum[tid] : 0;
    sh[tid] = v;
    __syncthreads();
#pragma unroll
    for (int off = 1; off < SCAN_BLK; off <<= 1) {
        int t = (tid >= off) ? sh[tid - off] : 0;
        __syncthreads();
        sh[tid] += t;
        __syncthreads();
    }
    if (tid < nblk) g_bsum[tid] = sh[tid] - v;    // exclusive
}

// Phase C: add block offsets; also writes g_off[N] = E
__global__ void scanC(int N, int E) {
    int gi = blockIdx.x * SCAN_BLK + threadIdx.x;
    if (gi < N) g_off[gi] += g_bsum[blockIdx.x];
    if (gi == 0) g_off[N] = E;
}

__global__ void csr_fill(const int* __restrict__ ei, int E) {
    int e = blockIdx.x * blockDim.x + threadIdx.x;
    if (e >= E) return;
    int s = ei[e];
    int t = ei[E + e];
    int pos = atomicAdd(&g_cnt[t], -1) - 1;   // unique slot in [0, deg)
    g_csr[g_off[t] + pos] = s;
}

// ---------------------------------------------------------------------------
// Aggregation: one warp per node; gather h[src] rows via CSR, write mean.
// csr indices loaded uniformly (L1 broadcast); 4 independent row streams.
// ---------------------------------------------------------------------------
__global__ void gather_agg(int xsel, int N) {
    int gt = blockIdx.x * blockDim.x + threadIdx.x;
    int node = gt >> 5;
    if (node >= N) return;
    int lane = gt & 31;
    const float* __restrict__ h = xsel ? g_x1 : g_h0;
    const int col = lane << 2;

    int beg = g_off[node];
    int end = g_off[node + 1];
    float4 a0 = make_float4(0.f, 0.f, 0.f, 0.f);
    float4 a1 = make_float4(0.f, 0.f, 0.f, 0.f);
    float4 a2 = make_float4(0.f, 0.f, 0.f, 0.f);
    float4 a3 = make_float4(0.f, 0.f, 0.f, 0.f);

    int i = beg;
    for (; i + 4 <= end; i += 4) {
        int s0 = __ldg(&g_csr[i + 0]);
        int s1 = __ldg(&g_csr[i + 1]);
        int s2 = __ldg(&g_csr[i + 2]);
        int s3 = __ldg(&g_csr[i + 3]);
        float4 v0 = *(const float4*)(h + (size_t)s0 * H + col);
        float4 v1 = *(const float4*)(h + (size_t)s1 * H + col);
        float4 v2 = *(const float4*)(h + (size_t)s2 * H + col);
        float4 v3 = *(const float4*)(h + (size_t)s3 * H + col);
        a0.x += v0.x; a0.y += v0.y; a0.z += v0.z; a0.w += v0.w;
        a1.x += v1.x; a1.y += v1.y; a1.z += v1.z; a1.w += v1.w;
        a2.x += v2.x; a2.y += v2.y; a2.z += v2.z; a2.w += v2.w;
        a3.x += v3.x; a3.y += v3.y; a3.z += v3.z; a3.w += v3.w;
    }
    for (; i < end; i++) {
        int s0 = __ldg(&g_csr[i]);
        float4 v0 = *(const float4*)(h + (size_t)s0 * H + col);
        a0.x += v0.x; a0.y += v0.y; a0.z += v0.z; a0.w += v0.w;
    }
    float inv = 1.0f / (float)max(end - beg, 1);
    float4 r;
    r.x = (a0.x + a1.x + a2.x + a3.x) * inv;
    r.y = (a0.y + a1.y + a2.y + a3.y) * inv;
    r.z = (a0.z + a1.z + a2.z + a3.z) * inv;
    r.w = (a0.w + a1.w + a2.w + a3.w) * inv;
    *(float4*)(g_agg + (size_t)node * H + col) = r;
}

// ---------------------------------------------------------------------------
// Register-tiled accumulate with FFMA2: 8 nodes x 8 outputs per thread.
// ---------------------------------------------------------------------------
__device__ __forceinline__ void mm_accum8(const float* __restrict__ Xs,
                                          const float* __restrict__ Ws,
                                          int n0, int jlo, ull acc[8][4]) {
#pragma unroll
    for (int k4 = 0; k4 < H; k4 += 4) {
        float4 xv[8];
#pragma unroll
        for (int i = 0; i < 8; i++)
            xv[i] = *(const float4*)(Xs + (n0 + i) * H + k4);
#pragma unroll
        for (int kk = 0; kk < 4; kk++) {
            const int k = k4 + kk;
            ulonglong2 wa = *(const ulonglong2*)(Ws + k * H + jlo);
            ulonglong2 wb = *(const ulonglong2*)(Ws + k * H + jlo + 64);
#pragma unroll
            for (int i = 0; i < 8; i++) {
                float xs = (kk == 0) ? xv[i].x : (kk == 1) ? xv[i].y
                         : (kk == 2) ? xv[i].z : xv[i].w;
                ull x2 = splat2(xs);
                fma2(acc[i][0], x2, wa.x);
                fma2(acc[i][1], x2, wa.y);
                fma2(acc[i][2], x2, wb.x);
                fma2(acc[i][3], x2, wb.y);
            }
        }
    }
}

// ---------------------------------------------------------------------------
// Input layer: h0 = relu( concat(attr,cc,bl,exist) @ W_in^T + b_in )
// ---------------------------------------------------------------------------
__global__ void __launch_bounds__(NTG, 2)
input_gemm(const float* __restrict__ attr, int ATTR,
           const float* __restrict__ cc,
           const float* __restrict__ bl,
           const float* __restrict__ exist,
           const float* __restrict__ b, int N) {
    extern __shared__ float sm[];
    float* Xs = sm;              // TILE_N * H
    float* Ws = sm + TILE_N * H; // HH
    const int tid = threadIdx.x;
    const int nb = blockIdx.x * TILE_N;

    for (int idx = tid; idx < HH / 4; idx += NTG)
        ((float4*)Ws)[idx] = ((const float4*)g_wt)[idx];  // slot 0

    for (int idx = tid; idx < TILE_N * H; idx += NTG) {
        int n = idx >> 7, k = idx & 127;
        int gn = nb + n;
        float v = 0.f;
        if (gn < N) {
            if (k < ATTR)            v = attr[(size_t)gn * ATTR + k];
            else if (k == ATTR)      v = cc[gn];
            else if (k == ATTR + 1)  v = bl[gn];
            else if (k == ATTR + 2)  v = exist[gn];
        }
        Xs[idx] = v;
    }
    __syncthreads();

    const int jt = tid & 15, nt = tid >> 4;
    const int jlo = jt * 4, n0 = nt * 8;
    ull acc[8][4] = {};
    mm_accum8(Xs, Ws, n0, jlo, acc);

#pragma unroll
    for (int i = 0; i < 8; i++) {
        int gn = nb + n0 + i;
        if (gn >= N) continue;
        float o[8];
        unpack2(acc[i][0], o[0], o[1]);
        unpack2(acc[i][1], o[2], o[3]);
        unpack2(acc[i][2], o[4], o[5]);
        unpack2(acc[i][3], o[6], o[7]);
        float4 o1, o2;
        o1.x = fmaxf(o[0] + b[jlo + 0], 0.f);
        o1.y = fmaxf(o[1] + b[jlo + 1], 0.f);
        o1.z = fmaxf(o[2] + b[jlo + 2], 0.f);
        o1.w = fmaxf(o[3] + b[jlo + 3], 0.f);
        o2.x = fmaxf(o[4] + b[jlo + 64], 0.f);
        o2.y = fmaxf(o[5] + b[jlo + 65], 0.f);
        o2.z = fmaxf(o[6] + b[jlo + 66], 0.f);
        o2.w = fmaxf(o[7] + b[jlo + 67], 0.f);
        *(float4*)(g_h0 + (size_t)gn * H + jlo) = o1;
        *(float4*)(g_h0 + (size_t)gn * H + jlo + 64) = o2;
    }
}

// ---------------------------------------------------------------------------
// SAGE layer: out = post( X@Ws^T + bs + mean@Wn^T + bn ); g_agg holds mean.
// ---------------------------------------------------------------------------
__global__ void __launch_bounds__(NTG, 2)
sage_gemm(int xsel, int wslot_self, int wslot_neigh,
          const float* __restrict__ bs,
          const float* __restrict__ bn,
          const float* __restrict__ exist,
          float* out, int N, int do_relu) {
    extern __shared__ float sm[];
    float* Xs = sm;
    float* Ws = sm + TILE_N * H;
    const int tid = threadIdx.x;
    const int nb = blockIdx.x * TILE_N;
    const int jt = tid & 15, nt = tid >> 4;
    const int jlo = jt * 4, n0 = nt * 8;
    const float* Xself = xsel ? g_x1 : g_h0;
    float* dst = out ? out : g_x1;

    ull acc[8][4] = {};

    // phase 1: self term
    for (int idx = tid; idx < HH / 4; idx += NTG)
        ((float4*)Ws)[idx] = ((const float4*)(g_wt + wslot_self * HH))[idx];
    for (int idx = tid; idx < TILE_N * (H / 4); idx += NTG) {
        int n = idx >> 5, kq = idx & 31;
        int gn = nb + n;
        float4 v = make_float4(0.f, 0.f, 0.f, 0.f);
        if (gn < N) v = *(const float4*)(Xself + (size_t)gn * H + kq * 4);
        *(float4*)(Xs + n * H + kq * 4) = v;
    }
    __syncthreads();
    mm_accum8(Xs, Ws, n0, jlo, acc);
    __syncthreads();

    // phase 2: neighbor-mean term (g_agg already normalized)
    for (int idx = tid; idx < HH / 4; idx += NTG)
        ((float4*)Ws)[idx] = ((const float4*)(g_wt + wslot_neigh * HH))[idx];
    for (int idx = tid; idx < TILE_N * (H / 4); idx += NTG) {
        int n = idx >> 5, kq = idx & 31;
        int gn = nb + n;
        float4 v = make_float4(0.f, 0.f, 0.f, 0.f);
        if (gn < N) v = *(const float4*)(g_agg + (size_t)gn * H + kq * 4);
        *(float4*)(Xs + n * H + kq * 4) = v;
    }
    __syncthreads();
    mm_accum8(Xs, Ws, n0, jlo, acc);

#pragma unroll
    for (int i = 0; i < 8; i++) {
        int gn = nb + n0 + i;
        if (gn >= N) continue;
        float ex = exist[gn];
        float o[8];
        unpack2(acc[i][0], o[0], o[1]);
        unpack2(acc[i][1], o[2], o[3]);
        unpack2(acc[i][2], o[4], o[5]);
        unpack2(acc[i][3], o[6], o[7]);
        float r[8];
#pragma unroll
        for (int q = 0; q < 4; q++) {
            float v1 = o[q] + bs[jlo + q] + bn[jlo + q];
            float v2 = o[q + 4] + bs[jlo + 64 + q] + bn[jlo + 64 + q];
            if (do_relu) { v1 = fmaxf(v1, 0.f); v2 = fmaxf(v2, 0.f); }
            r[q] = v1 * ex;
            r[q + 4] = v2 * ex;
        }
        *(float4*)(dst + (size_t)gn * H + jlo) = make_float4(r[0], r[1], r[2], r[3]);
        *(float4*)(dst + (size_t)gn * H + jlo + 64) = make_float4(r[4], r[5], r[6], r[7]);
    }
}

// ---------------------------------------------------------------------------
extern "C" void kernel_launch(void* const* d_in, const int* in_sizes, int n_in,
                              void* d_out, int out_size) {
    const float* attr  = (const float*)d_in[0];
    const float* cc    = (const float*)d_in[1];
    const float* bl    = (const float*)d_in[2];
    const float* exist = (const float*)d_in[3];
    const float* W_in  = (const float*)d_in[4];
    const float* b_in  = (const float*)d_in[5];
    const float* W1s   = (const float*)d_in[6];
    const float* b1s   = (const float*)d_in[7];
    const float* W1n   = (const float*)d_in[8];
    const float* b1n   = (const float*)d_in[9];
    const float* W2s   = (const float*)d_in[10];
    const float* b2s   = (const float*)d_in[11];
    const float* W2n   = (const float*)d_in[12];
    const float* b2n   = (const float*)d_in[13];
    const int*   ei    = (const int*)d_in[14];   // int32 (JAX x64 disabled)

    const int N    = in_sizes[3];
    const int ATTR = in_sizes[0] / N;
    const int E    = in_sizes[14] / 2;
    float* out = (float*)d_out;

    const int SMEM = (TILE_N * H + HH) * (int)sizeof(float);
    cudaFuncSetAttribute(input_gemm, cudaFuncAttributeMaxDynamicSharedMemorySize, SMEM);
    cudaFuncSetAttribute(sage_gemm,  cudaFuncAttributeMaxDynamicSharedMemorySize, SMEM);

    const int gemm_grid = (N + TILE_N - 1) / TILE_N;
    const int edge_grid = (E + NT - 1) / NT;
    const int scan_grid = (N + SCAN_BLK - 1) / SCAN_BLK;
    const long long ga_threads = (long long)N * 32;
    const int ga_grid = (int)((ga_threads + NT - 1) / NT);

    // weight transposes + zero g_cnt — one launch
    dim3 tr_grid((HH + NT - 1) / NT, 5);
    transpose_w_all<<<tr_grid, NT>>>(W_in, W1s, W1n, W2s, W2n, N);

    // CSR build (shared by both layers)
    deg_hist<<<edge_grid, NT>>>(ei, E);
    scanA<<<scan_grid, SCAN_BLK>>>(N);
    scanB<<<1, SCAN_BLK>>>(scan_grid);
    scanC<<<scan_grid, SCAN_BLK>>>(N, E);
    csr_fill<<<edge_grid, NT>>>(ei, E);

    // input layer
    input_gemm<<<gemm_grid, NTG, SMEM>>>(attr, ATTR, cc, bl, exist, b_in, N);

    // layer 1
    gather_agg<<<ga_grid, NT>>>(0, N);
    sage_gemm<<<gemm_grid, NTG, SMEM>>>(0, 1, 2, b1s, b1n, exist, nullptr, N, 1);

    // layer 2
    gather_agg<<<ga_grid, NT>>>(1, N);
    sage_gemm<<<gemm_grid, NTG, SMEM>>>(1, 3, 4, b2s, b2n, exist, out, N, 0);
}